// round 15
// baseline (speedup 1.0000x reference)
#include <cuda_runtime.h>
#include <cuda_fp16.h>
#include <cuda_bf16.h>
#include <cstdint>
#include <cstring>

#define NN 100000
#define FDIM 128
#define BM 128
#define BKK 32
#define SSTRIDE 36    // fp32 tiles: BKK + 4
#define HSTRIDE 40    // fp16 A tile rows
#define EMAX 1600000
#define PBLK 592                         // 4 blocks/SM x 148 SMs
#define CHUNK ((NN + PBLK - 1) / PBLK)   // 169 (<= 256)

// ---- scratch (device globals) ----
__device__ float    g_agg[(size_t)NN * FDIM];
__device__ __half   g_hh[(size_t)NN * FDIM];
__device__ __half   g_xh[(size_t)NN * FDIM];
__device__ float    g_sum[FDIM];
__device__ float    g_sq[FDIM];
__device__ int      g_ei64;
__device__ int      g_cnt[NN];
__device__ int      g_rowptr[NN + 1];
__device__ int      g_bsum[PBLK];
__device__ int      g_src[EMAX];
__device__ unsigned g_arrive;            // monotonic grid-barrier counter

// ---------------------------------------------------------------------------
__device__ __forceinline__ uint32_t h2_bits(__half2 h) {
    uint32_t u; memcpy(&u, &h, 4); return u;
}
__device__ __forceinline__ __half2 bits_h2(uint32_t u) {
    __half2 h; memcpy(&h, &u, 4); return h;
}

__device__ __forceinline__ uint32_t f2tf32(float f) {
    uint32_t u;
    asm("cvt.rna.tf32.f32 %0, %1;" : "=r"(u) : "f"(f));
    return u;
}

__device__ __forceinline__ void mma_tf32(float c[4],
                                         uint32_t a0, uint32_t a1, uint32_t a2, uint32_t a3,
                                         uint32_t b0, uint32_t b1) {
    asm volatile(
        "mma.sync.aligned.m16n8k8.row.col.f32.tf32.tf32.f32 "
        "{%0,%1,%2,%3}, {%4,%5,%6,%7}, {%8,%9}, {%0,%1,%2,%3};"
        : "+f"(c[0]), "+f"(c[1]), "+f"(c[2]), "+f"(c[3])
        : "r"(a0), "r"(a1), "r"(a2), "r"(a3), "r"(b0), "r"(b1));
}

__device__ __forceinline__ void cp_async16(void* smem_dst, const void* gmem_src, int bytes) {
    uint32_t d = (uint32_t)__cvta_generic_to_shared(smem_dst);
    asm volatile("cp.async.ca.shared.global [%0], [%1], 16, %2;"
                 :: "r"(d), "l"(gmem_src), "r"(bytes) : "memory");
}

__device__ __forceinline__ int edge_at(const void* ei_raw, long long pos) {
    if (g_ei64) return (int)__ldg(((const long long*)ei_raw) + pos);
    return __ldg(((const int*)ei_raw) + pos);
}

// software grid barrier: monotonic counter, safe across graph replays
__device__ __forceinline__ void gsync() {
    __syncthreads();
    __threadfence();
    if (threadIdx.x == 0) {
        unsigned old = atomicAdd(&g_arrive, 1u);
        unsigned target = (old / PBLK + 1u) * PBLK;
        while (atomicAdd(&g_arrive, 0u) < target) __nanosleep(32);
    }
    __syncthreads();
}

// ---------------------------------------------------------------------------
// Persistent prep kernel: zero+detect | hist+x2h | scan | offsets | reorder | gather
// ---------------------------------------------------------------------------
__global__ __launch_bounds__(256, 4) void prep_kernel(const float* __restrict__ x,
                                                      const void* __restrict__ ei,
                                                      int E,
                                                      const float* __restrict__ eps) {
    const int tid  = threadIdx.x;
    const int b    = blockIdx.x;
    const int gt   = b * 256 + tid;
    const int GSZ  = PBLK * 256;
    __shared__ int sred[256];
    __shared__ int ws[8];

    // ---- P0: zero counters / BN accumulators, dtype probe ----
    for (int i = gt; i < NN; i += GSZ) g_cnt[i] = 0;
    if (gt < FDIM) { g_sum[gt] = 0.f; g_sq[gt] = 0.f; }
    if (gt == 0) {
        int ok64 = 1;
        const long long* e64 = (const long long*)ei;
        for (int k = 0; k < 64; ++k) {
            long long v = e64[k];
            if (v < 0 || v >= NN) { ok64 = 0; break; }
        }
        g_ei64 = ok64;
    }
    gsync();

    // ---- P1: histogram + fp16 mirror of x (independent; overlap) ----
    for (int e = gt; e < E; e += GSZ) {
        int r = edge_at(ei, e);
        if ((unsigned)r < NN) atomicAdd(&g_cnt[r], 1);
    }
    {
        const int total4 = NN * FDIM / 4;
        const float4* x4 = (const float4*)x;
        for (int i = gt; i < total4; i += GSZ) {
            float4 v = __ldg(x4 + i);
            __half2 h0 = __floats2half2_rn(v.x, v.y);
            __half2 h1 = __floats2half2_rn(v.z, v.w);
            ((uint2*)g_xh)[i] = make_uint2(h2_bits(h0), h2_bits(h1));
        }
    }
    gsync();

    // ---- P2: per-block local exclusive scan of its CHUNK ----
    {
        int start = b * CHUNK;
        int i = start + tid;
        int v = (tid < CHUNK && i < NN) ? g_cnt[i] : 0;
        int lane = tid & 31, w = tid >> 5;
        int incl = v;
#pragma unroll
        for (int o = 1; o < 32; o <<= 1) {
            int t = __shfl_up_sync(~0u, incl, o);
            if (lane >= o) incl += t;
        }
        if (lane == 31) ws[w] = incl;
        __syncthreads();
        if (w == 0) {
            int wv = (lane < 8) ? ws[lane] : 0;
            int wi = wv;
#pragma unroll
            for (int o = 1; o < 8; o <<= 1) {
                int t = __shfl_up_sync(0xffu, wi, o);
                if (lane >= o && lane < 8) wi += t;
            }
            if (lane < 8) ws[lane] = wi - wv;   // exclusive warp offsets
        }
        __syncthreads();
        int excl = incl - v + ws[w];
        if (tid < CHUNK && i < NN) g_rowptr[i] = excl;      // local (no global offset yet)
        if (tid == 255) g_bsum[b] = ws[7] + incl;           // block total
    }
    gsync();

    // ---- P3: add global offsets, init cursors, write grand total ----
    {
        int limit = (b == 0) ? PBLK : b;
        int acc = 0;
        for (int k = tid; k < limit; k += 256) acc += g_bsum[k];
        sred[tid] = acc;
        __syncthreads();
        for (int s = 128; s; s >>= 1) {
            if (tid < s) sred[tid] += sred[tid + s];
            __syncthreads();
        }
        int val = sred[0];
        int offset = (b == 0) ? 0 : val;
        if (b == 0 && tid == 0) g_rowptr[NN] = val;
        int start = b * CHUNK;
        int i = start + tid;
        if (tid < CHUNK && i < NN) {
            int e = g_rowptr[i] + offset;
            g_rowptr[i] = e;
            g_cnt[i] = e;    // cursor for reorder
        }
    }
    gsync();

    // ---- P4: reorder sources by destination ----
    for (int e = gt; e < E; e += GSZ) {
        int r = edge_at(ei, e);
        int c = edge_at(ei, (long long)E + e);
        if ((unsigned)r >= NN || (unsigned)c >= NN) continue;
        int pos = atomicAdd(&g_cnt[r], 1);
        if ((unsigned)pos < EMAX) g_src[pos] = c;
    }
    gsync();

    // ---- P5: gather-accumulate (warp per node, unroll-8) ----
    {
        int lane = tid & 31;
        int gw0 = b * 8 + (tid >> 5);
        float cc = 1.0f + __ldg(eps);
        const uint2* xh = (const uint2*)g_xh;
        for (int gw = gw0; gw < NN; gw += PBLK * 8) {
            int beg = __ldg(&g_rowptr[gw]);
            int end = __ldg(&g_rowptr[gw + 1]);
            float4 v = __ldg(((const float4*)(x + (size_t)gw * FDIM)) + lane);
            float4 acc = make_float4(v.x * cc, v.y * cc, v.z * cc, v.w * cc);
            int j = beg;
            for (; j + 8 <= end; j += 8) {
                int si[8];
#pragma unroll
                for (int u = 0; u < 8; ++u) si[u] = __ldg(&g_src[j + u]);
                uint2 p[8];
#pragma unroll
                for (int u = 0; u < 8; ++u) p[u] = __ldg(xh + (size_t)si[u] * (FDIM / 4) + lane);
#pragma unroll
                for (int u = 0; u < 8; ++u) {
                    float2 e0 = __half22float2(bits_h2(p[u].x));
                    float2 e1 = __half22float2(bits_h2(p[u].y));
                    acc.x += e0.x; acc.y += e0.y; acc.z += e1.x; acc.w += e1.y;
                }
            }
            if (j + 4 <= end) {
                int si[4];
#pragma unroll
                for (int u = 0; u < 4; ++u) si[u] = __ldg(&g_src[j + u]);
                uint2 p[4];
#pragma unroll
                for (int u = 0; u < 4; ++u) p[u] = __ldg(xh + (size_t)si[u] * (FDIM / 4) + lane);
#pragma unroll
                for (int u = 0; u < 4; ++u) {
                    float2 e0 = __half22float2(bits_h2(p[u].x));
                    float2 e1 = __half22float2(bits_h2(p[u].y));
                    acc.x += e0.x; acc.y += e0.y; acc.z += e1.x; acc.w += e1.y;
                }
                j += 4;
            }
            for (; j < end; ++j) {
                int s0 = __ldg(&g_src[j]);
                uint2 p0 = __ldg(xh + (size_t)s0 * (FDIM / 4) + lane);
                float2 e0 = __half22float2(bits_h2(p0.x));
                float2 e1 = __half22float2(bits_h2(p0.y));
                acc.x += e0.x; acc.y += e0.y; acc.z += e1.x; acc.w += e1.y;
            }
            ((float4*)(g_agg + (size_t)gw * FDIM))[lane] = acc;
        }
    }
}

// ---------------------------------------------------------------------------
// GEMM1 (tf32, cp.async double-buffered): h(fp16) = agg @ W1^T + b1, + BN stats
// ---------------------------------------------------------------------------
__global__ __launch_bounds__(256) void gemm1_kernel(const float* __restrict__ W1,
                                                    const float* __restrict__ b1) {
    __shared__ float s_a[2][BM][SSTRIDE];
    __shared__ float s_w[2][FDIM][SSTRIDE];
    __shared__ float sh_sum[FDIM];
    __shared__ float sh_sq[FDIM];

    const int tid  = threadIdx.x;
    const int lane = tid & 31;
    const int wid  = tid >> 5;
    const int wm   = wid >> 1;
    const int wn   = wid & 1;
    const int gid  = lane >> 2;
    const int tig  = lane & 3;
    const int row0 = blockIdx.x * BM;

    if (tid < FDIM) { sh_sum[tid] = 0.f; sh_sq[tid] = 0.f; }

    auto load_tile = [&](int kt, int s) {
#pragma unroll
        for (int it = 0; it < 4; ++it) {
            int idx = it * 256 + tid;
            int r   = idx >> 3;
            int kk  = (idx & 7) * 4;
            int grow = row0 + r;
            const float* asrc = (grow < NN)
                ? &g_agg[(size_t)grow * FDIM + kt + kk] : g_agg;
            cp_async16(&s_a[s][r][kk], asrc, (grow < NN) ? 16 : 0);
            cp_async16(&s_w[s][r][kk], &W1[(size_t)r * FDIM + kt + kk], 16);
        }
        asm volatile("cp.async.commit_group;" ::: "memory");
    };

    float c[2][8][4];
#pragma unroll
    for (int mt = 0; mt < 2; ++mt)
#pragma unroll
        for (int nt = 0; nt < 8; ++nt)
#pragma unroll
            for (int j = 0; j < 4; ++j) c[mt][nt][j] = 0.f;

    load_tile(0, 0);
#pragma unroll
    for (int kti = 0; kti < 4; ++kti) {
        const int s = kti & 1;
        if (kti < 3) load_tile((kti + 1) * BKK, 1 - s);
        if (kti < 3) asm volatile("cp.async.wait_group 1;" ::: "memory");
        else         asm volatile("cp.async.wait_group 0;" ::: "memory");
        __syncthreads();

#pragma unroll
        for (int ks = 0; ks < 4; ++ks) {
            int k0 = ks * 8;
            uint32_t af[2][4];
#pragma unroll
            for (int mt = 0; mt < 2; ++mt) {
                int rb = wm * 32 + mt * 16 + gid;
                af[mt][0] = f2tf32(s_a[s][rb][k0 + tig]);
                af[mt][1] = f2tf32(s_a[s][rb + 8][k0 + tig]);
                af[mt][2] = f2tf32(s_a[s][rb][k0 + tig + 4]);
                af[mt][3] = f2tf32(s_a[s][rb + 8][k0 + tig + 4]);
            }
#pragma unroll
            for (int nt = 0; nt < 8; ++nt) {
                int nb = wn * 64 + nt * 8 + gid;
                uint32_t bb0 = f2tf32(s_w[s][nb][k0 + tig]);
                uint32_t bb1 = f2tf32(s_w[s][nb][k0 + tig + 4]);
                mma_tf32(c[0][nt], af[0][0], af[0][1], af[0][2], af[0][3], bb0, bb1);
                mma_tf32(c[1][nt], af[1][0], af[1][1], af[1][2], af[1][3], bb0, bb1);
            }
        }
        __syncthreads();
    }

    float psum[8][2], psq[8][2];
#pragma unroll
    for (int nt = 0; nt < 8; ++nt) {
        psum[nt][0] = 0.f; psum[nt][1] = 0.f;
        psq[nt][0] = 0.f;  psq[nt][1] = 0.f;
    }

#pragma unroll
    for (int nt = 0; nt < 8; ++nt) {
        int col = wn * 64 + nt * 8 + 2 * tig;
        float2 bb = __ldg((const float2*)&b1[col]);
#pragma unroll
        for (int mt = 0; mt < 2; ++mt) {
            int r0g = row0 + wm * 32 + mt * 16 + gid;
            if (r0g < NN) {
                float h0 = c[mt][nt][0] + bb.x;
                float h1 = c[mt][nt][1] + bb.y;
                *(uint32_t*)&g_hh[(size_t)r0g * FDIM + col] =
                    h2_bits(__floats2half2_rn(h0, h1));
                psum[nt][0] += h0; psum[nt][1] += h1;
                psq[nt][0] += h0 * h0; psq[nt][1] += h1 * h1;
            }
            int r1g = r0g + 8;
            if (r1g < NN) {
                float h0 = c[mt][nt][2] + bb.x;
                float h1 = c[mt][nt][3] + bb.y;
                *(uint32_t*)&g_hh[(size_t)r1g * FDIM + col] =
                    h2_bits(__floats2half2_rn(h0, h1));
                psum[nt][0] += h0; psum[nt][1] += h1;
                psq[nt][0] += h0 * h0; psq[nt][1] += h1 * h1;
            }
        }
    }

#pragma unroll
    for (int off = 16; off >= 4; off >>= 1) {
#pragma unroll
        for (int nt = 0; nt < 8; ++nt) {
#pragma unroll
            for (int j = 0; j < 2; ++j) {
                psum[nt][j] += __shfl_xor_sync(0xffffffffu, psum[nt][j], off);
                psq[nt][j]  += __shfl_xor_sync(0xffffffffu, psq[nt][j], off);
            }
        }
    }
    if (gid == 0) {
#pragma unroll
        for (int nt = 0; nt < 8; ++nt) {
            int col = wn * 64 + nt * 8 + 2 * tig;
            atomicAdd(&sh_sum[col],     psum[nt][0]);
            atomicAdd(&sh_sum[col + 1], psum[nt][1]);
            atomicAdd(&sh_sq[col],      psq[nt][0]);
            atomicAdd(&sh_sq[col + 1],  psq[nt][1]);
        }
    }
    __syncthreads();
    if (tid < FDIM) {
        atomicAdd(&g_sum[tid], sh_sum[tid]);
        atomicAdd(&g_sq[tid],  sh_sq[tid]);
    }
}

// ---------------------------------------------------------------------------
// GEMM2 (tf32, cp.async, fp16 A): out = relu(h*scale+shift) @ W2^T + b2
// BN finalize inlined per block (g_sum/g_sq -> scale/shift).
// ---------------------------------------------------------------------------
__global__ __launch_bounds__(256) void gemm2_kernel(const float* __restrict__ W2,
                                                    const float* __restrict__ b2,
                                                    const float* __restrict__ gamma,
                                                    const float* __restrict__ beta,
                                                    float* __restrict__ out) {
    __shared__ __half s_a[2][BM][HSTRIDE];
    __shared__ float  s_w[2][FDIM][SSTRIDE];
    __shared__ float  ss_scale[FDIM];
    __shared__ float  ss_shift[FDIM];

    const int tid  = threadIdx.x;
    const int lane = tid & 31;
    const int wid  = tid >> 5;
    const int wm   = wid >> 1;
    const int wn   = wid & 1;
    const int gid  = lane >> 2;
    const int tig  = lane & 3;
    const int row0 = blockIdx.x * BM;

    if (tid < FDIM) {
        float invn = 1.0f / (float)NN;
        float mean = g_sum[tid] * invn;
        float var  = g_sq[tid] * invn - mean * mean;
        float rstd = rsqrtf(var + 1e-5f);
        float sc   = rstd * __ldg(&gamma[tid]);
        ss_scale[tid] = sc;
        ss_shift[tid] = __ldg(&beta[tid]) - mean * sc;
    }

    auto load_tile = [&](int kt, int s) {
#pragma unroll
        for (int it = 0; it < 2; ++it) {
            int idx = it * 256 + tid;
            int r   = idx >> 2;
            int kk  = (idx & 3) * 8;
            int grow = row0 + r;
            const __half* asrc = (grow < NN)
                ? &g_hh[(size_t)grow * FDIM + kt + kk] : g_hh;
            cp_async16(&s_a[s][r][kk], asrc, (grow < NN) ? 16 : 0);
        }
#pragma unroll
        for (int it = 0; it < 4; ++it) {
            int idx = it * 256 + tid;
            int r   = idx >> 3;
            int kk  = (idx & 7) * 4;
            cp_async16(&s_w[s][r][kk], &W2[(size_t)r * FDIM + kt + kk], 16);
        }
        asm volatile("cp.async.commit_group;" ::: "memory");
    };

    float c[2][8][4];
#pragma unroll
    for (int mt = 0; mt < 2; ++mt)
#pragma unroll
        for (int nt = 0; nt < 8; ++nt)
#pragma unroll
            for (int j = 0; j < 4; ++j) c[mt][nt][j] = 0.f;

    load_tile(0, 0);
#pragma unroll
    for (int kti = 0; kti < 4; ++kti) {
        const int s = kti & 1;
        if (kti < 3) load_tile((kti + 1) * BKK, 1 - s);
        if (kti < 3) asm volatile("cp.async.wait_group 1;" ::: "memory");
        else         asm volatile("cp.async.wait_group 0;" ::: "memory");
        __syncthreads();

        const int ktg = kti * BKK;
#pragma unroll
        for (int ks = 0; ks < 4; ++ks) {
            int k0 = ks * 8;
            int kg0 = ktg + k0 + tig;
            float sc0 = ss_scale[kg0],     sh0 = ss_shift[kg0];
            float sc1 = ss_scale[kg0 + 4], sh1 = ss_shift[kg0 + 4];
            uint32_t af[2][4];
#pragma unroll
            for (int mt = 0; mt < 2; ++mt) {
                int rb = wm * 32 + mt * 16 + gid;
                float a0 = __half2float(s_a[s][rb][k0 + tig]);
                float a1 = __half2float(s_a[s][rb + 8][k0 + tig]);
                float a2 = __half2float(s_a[s][rb][k0 + tig + 4]);
                float a3 = __half2float(s_a[s][rb + 8][k0 + tig + 4]);
                af[mt][0] = f2tf32(fmaxf(fmaf(a0, sc0, sh0), 0.f));
                af[mt][1] = f2tf32(fmaxf(fmaf(a1, sc0, sh0), 0.f));
                af[mt][2] = f2tf32(fmaxf(fmaf(a2, sc1, sh1), 0.f));
                af[mt][3] = f2tf32(fmaxf(fmaf(a3, sc1, sh1), 0.f));
            }
#pragma unroll
            for (int nt = 0; nt < 8; ++nt) {
                int nb = wn * 64 + nt * 8 + gid;
                uint32_t bb0 = f2tf32(s_w[s][nb][k0 + tig]);
                uint32_t bb1 = f2tf32(s_w[s][nb][k0 + tig + 4]);
                mma_tf32(c[0][nt], af[0][0], af[0][1], af[0][2], af[0][3], bb0, bb1);
                mma_tf32(c[1][nt], af[1][0], af[1][1], af[1][2], af[1][3], bb0, bb1);
            }
        }
        __syncthreads();
    }

#pragma unroll
    for (int nt = 0; nt < 8; ++nt) {
        int col = wn * 64 + nt * 8 + 2 * tig;
        float2 bb = __ldg((const float2*)&b2[col]);
#pragma unroll
        for (int mt = 0; mt < 2; ++mt) {
            int r0g = row0 + wm * 32 + mt * 16 + gid;
            if (r0g < NN) {
                *(float2*)&out[(size_t)r0g * FDIM + col] =
                    make_float2(c[mt][nt][0] + bb.x, c[mt][nt][1] + bb.y);
            }
            int r1g = r0g + 8;
            if (r1g < NN) {
                *(float2*)&out[(size_t)r1g * FDIM + col] =
                    make_float2(c[mt][nt][2] + bb.x, c[mt][nt][3] + bb.y);
            }
        }
    }
}

// ---------------------------------------------------------------------------
extern "C" void kernel_launch(void* const* d_in, const int* in_sizes, int n_in,
                              void* d_out, int out_size) {
    int idx_x = -1, idx_e = -1, idx_eps = -1;
    int mats[2] = {-1, -1}; int nm = 0;
    int vecs[4] = {-1, -1, -1, -1}; int nv = 0;
    for (int i = 0; i < n_in; ++i) {
        int s = in_sizes[i];
        if (s == NN * FDIM)             idx_x = i;
        else if (s == 1)                idx_eps = i;
        else if (s == FDIM * FDIM)      { if (nm < 2) mats[nm++] = i; }
        else if (s == FDIM)             { if (nv < 4) vecs[nv++] = i; }
        else                            idx_e = i;
    }

    const float* x     = (const float*)d_in[idx_x];
    const void*  ei    = d_in[idx_e];
    const float* eps   = (const float*)d_in[idx_eps];
    const float* W1    = (const float*)d_in[mats[0]];
    const float* W2    = (const float*)d_in[mats[1]];
    const float *b1, *gamma, *beta, *b2;
    if (idx_x == 0) {          // dict order: x, edge, eps, W1, b1, gamma, beta, W2, b2
        b1    = (const float*)d_in[vecs[0]];
        gamma = (const float*)d_in[vecs[1]];
        beta  = (const float*)d_in[vecs[2]];
        b2    = (const float*)d_in[vecs[3]];
    } else {                   // alphabetical order
        b1    = (const float*)d_in[vecs[0]];
        b2    = (const float*)d_in[vecs[1]];
        beta  = (const float*)d_in[vecs[2]];
        gamma = (const float*)d_in[vecs[3]];
    }
    float* out = (float*)d_out;

    const int E = in_sizes[idx_e] / 2;

    prep_kernel<<<PBLK, 256>>>(x, ei, E, eps);

    const int gblocks = (NN + BM - 1) / BM;
    gemm1_kernel<<<gblocks, 256>>>(W1, b1);
    gemm2_kernel<<<gblocks, 256>>>(W2, b2, gamma, beta, out);
}